// round 3
// baseline (speedup 1.0000x reference)
#include <cuda_runtime.h>

// BilateralGrid slice + apply.
// Inputs (metadata order): rgb f32 (3,1080,1920), grids f32 (1,16,16,8,12), idx i32.
// Output: concat(affine_mat (H*W*12), res_rgb (H*W*3)) fp32.

#define HI 1080
#define WI 1920
#define HG 16
#define WG 16
#define LG 8
#define HW (HI * WI)
#define GRID_ELEMS (HG * WG * LG * 12)

__global__ __launch_bounds__(256, 8)
void bilateral_grid_kernel(const float* __restrict__ rgb,
                           const float* __restrict__ grids,
                           const int* __restrict__ idx,
                           float* __restrict__ out)
{
    int p = blockIdx.x * blockDim.x + threadIdx.x;
    if (p >= HW) return;

    int x = p % WI;
    int y = p / WI;

    float r = rgb[p];
    float g = rgb[HW + p];
    float b = rgb[2 * HW + p];

    float gray = 0.299f * r + 0.587f * g + 0.114f * b;

    // align_corners-style mapping (linspace(0, Hg-1, Hi))
    float gy = (float)y * ((float)(HG - 1) / (float)(HI - 1));
    float gx = (float)x * ((float)(WG - 1) / (float)(WI - 1));
    float gz = fminf(fmaxf(gray, 0.0f), 1.0f) * (float)(LG - 1);

    float fy = floorf(gy), wy = gy - fy;
    float fx = floorf(gx), wx = gx - fx;
    float fz = floorf(gz), wz = gz - fz;

    int y0 = min(max((int)fy, 0), HG - 1);
    int y1 = min(y0 + 1, HG - 1);
    int x0 = min(max((int)fx, 0), WG - 1);
    int x1 = min(x0 + 1, WG - 1);
    int z0 = min(max((int)fz, 0), LG - 1);
    int z1 = min(z0 + 1, LG - 1);

    const float* gbase = grids + (*idx) * GRID_ELEMS;

    float a[12];
#pragma unroll
    for (int i = 0; i < 12; i++) a[i] = 0.0f;

    const float wys[2] = {1.0f - wy, wy};
    const int   ys [2] = {y0, y1};
    const float wxs[2] = {1.0f - wx, wx};
    const int   xs [2] = {x0, x1};
    const float wz0 = 1.0f - wz;

#pragma unroll
    for (int iy = 0; iy < 2; iy++) {
#pragma unroll
        for (int ix = 0; ix < 2; ix++) {
            float wsp = wys[iy] * wxs[ix];
            float w0 = wsp * wz0;
            float w1 = wsp * wz;
            int cell = (ys[iy] * WG + xs[ix]) * LG;
            const float4* c0 = (const float4*)(gbase + (cell + z0) * 12);
            const float4* c1 = (const float4*)(gbase + (cell + z1) * 12);
#pragma unroll
            for (int q = 0; q < 3; q++) {
                float4 v0 = __ldg(c0 + q);
                float4 v1 = __ldg(c1 + q);
                a[4 * q + 0] += w0 * v0.x + w1 * v1.x;
                a[4 * q + 1] += w0 * v0.y + w1 * v1.y;
                a[4 * q + 2] += w0 * v0.z + w1 * v1.z;
                a[4 * q + 3] += w0 * v0.w + w1 * v1.w;
            }
        }
    }

    // affine_mat output: (H*W, 12) at out[0 .. HW*12)
    float4* ao = (float4*)(out + (size_t)p * 12);
    ao[0] = make_float4(a[0], a[1], a[2], a[3]);
    ao[1] = make_float4(a[4], a[5], a[6], a[7]);
    ao[2] = make_float4(a[8], a[9], a[10], a[11]);

    // res_rgb output: (H*W, 3) at out[HW*12 .. HW*15)
    float r0 = a[0] * r + a[1] * g + a[2]  * b + a[3];
    float r1 = a[4] * r + a[5] * g + a[6]  * b + a[7];
    float r2 = a[8] * r + a[9] * g + a[10] * b + a[11];

    float* ro = out + (size_t)HW * 12 + (size_t)p * 3;
    ro[0] = r0;
    ro[1] = r1;
    ro[2] = r2;
}

extern "C" void kernel_launch(void* const* d_in, const int* in_sizes, int n_in,
                              void* d_out, int out_size)
{
    const float* rgb   = (const float*)d_in[0];
    const float* grids = (const float*)d_in[1];
    const int*   idx   = (const int*)d_in[2];
    float* out = (float*)d_out;

    int threads = 256;
    int blocks = (HW + threads - 1) / threads;
    bilateral_grid_kernel<<<blocks, threads>>>(rgb, grids, idx, out);
}

// round 6
// speedup vs baseline: 1.8139x; 1.8139x over previous
#include <cuda_runtime.h>

// BilateralGrid slice + apply — smem-cached grid, y-lerp folded at fill time.
// Inputs: rgb f32 (3,1080,1920), grids f32 (1,16,16,8,12), idx i32.
// Output: concat(affine_mat (H*W*12), res_rgb (H*W*3)) fp32.

#define HI 1080
#define WI 1920
#define HG 16
#define WG 16
#define LG 8
#define HW (HI * WI)
#define GRID_ELEMS (HG * WG * LG * 12)
#define BLK 128                      // pixels (= threads) per block, one row
#define NXC 3                        // x-cells cached per block
#define STEP_X ((float)(WG - 1) / (float)(WI - 1))
#define STEP_Y ((float)(HG - 1) / (float)(HI - 1))

__global__ __launch_bounds__(BLK)
void bilateral_grid_kernel(const float* __restrict__ rgb,
                           const float* __restrict__ grids,
                           const int* __restrict__ idx,
                           float* __restrict__ out)
{
    // sg[xx][z][q] as float4: index (xx*8 + z)*3 + q   (xx<3, z<8, q<3)
    __shared__ float4 sg[NXC * LG * 3];   // 72 float4 = 1152 B

    const int tid = threadIdx.x;
    const int y   = blockIdx.y;
    const int xb  = blockIdx.x * BLK;

    // --- per-row y interpolation constants (uniform across block) ---
    float gy = (float)y * STEP_Y;
    int   y0 = min((int)gy, HG - 1);
    int   y1 = min(y0 + 1, HG - 1);
    float wy = gy - (float)y0;

    // first x-cell covered by this block
    const int xcb = (int)((float)xb * STEP_X);

    // --- fill smem: y-lerped 3x8x12 sub-grid ---
    const float4* g4 = (const float4*)(grids + (*idx) * GRID_ELEMS);
    if (tid < NXC * LG * 3) {
        int xx  = tid / (LG * 3);
        int rem = tid % (LG * 3);            // z*3 + q
        int xg  = min(xcb + xx, WG - 1);
        float4 v0 = __ldg(&g4[(y0 * WG + xg) * (LG * 3) + rem]);
        float4 v1 = __ldg(&g4[(y1 * WG + xg) * (LG * 3) + rem]);
        float4 o;
        o.x = fmaf(wy, v1.x - v0.x, v0.x);
        o.y = fmaf(wy, v1.y - v0.y, v0.y);
        o.z = fmaf(wy, v1.z - v0.z, v0.z);
        o.w = fmaf(wy, v1.w - v0.w, v0.w);
        sg[tid] = o;
    }
    __syncthreads();

    // --- per-pixel stage ---
    const int x = xb + tid;
    const int p = y * WI + x;

    float r = rgb[p];
    float g = rgb[HW + p];
    float b = rgb[2 * HW + p];

    float gray = fmaf(0.299f, r, fmaf(0.587f, g, 0.114f * b));
    float gz   = __saturatef(gray) * (float)(LG - 1);
    float fz   = floorf(gz);
    float wz   = gz - fz;
    int   z0   = min((int)fz, LG - 1);
    int   z1   = min(z0 + 1, LG - 1);

    float gx = (float)x * STEP_X;
    float fx = floorf(gx);
    float wx = gx - fx;
    int   x0 = min((int)fx, WG - 1);
    int   x1 = min(x0 + 1, WG - 1);
    int   x0r = x0 - xcb;                 // in [0,1]
    int   x1r = x1 - xcb;                 // in [0,2]

    float w00 = (1.0f - wx) * (1.0f - wz);
    float w01 = (1.0f - wx) * wz;
    float w10 = wx * (1.0f - wz);
    float w11 = wx * wz;

    const int b00 = x0r * (LG * 3) + z0 * 3;
    const int b01 = x0r * (LG * 3) + z1 * 3;
    const int b10 = x1r * (LG * 3) + z0 * 3;
    const int b11 = x1r * (LG * 3) + z1 * 3;

    float a[12];
#pragma unroll
    for (int q = 0; q < 3; q++) {
        float4 v00 = sg[b00 + q];
        float4 v01 = sg[b01 + q];
        float4 v10 = sg[b10 + q];
        float4 v11 = sg[b11 + q];
        a[4*q + 0] = w00*v00.x + w01*v01.x + w10*v10.x + w11*v11.x;
        a[4*q + 1] = w00*v00.y + w01*v01.y + w10*v10.y + w11*v11.y;
        a[4*q + 2] = w00*v00.z + w01*v01.z + w10*v10.z + w11*v11.z;
        a[4*q + 3] = w00*v00.w + w01*v01.w + w10*v10.w + w11*v11.w;
    }

    // affine_mat output: (H*W, 12)
    float4* ao = (float4*)(out + (size_t)p * 12);
    ao[0] = make_float4(a[0], a[1], a[2],  a[3]);
    ao[1] = make_float4(a[4], a[5], a[6],  a[7]);
    ao[2] = make_float4(a[8], a[9], a[10], a[11]);

    // res_rgb output: (H*W, 3)
    float r0 = fmaf(a[0], r, fmaf(a[1], g, fmaf(a[2],  b, a[3])));
    float r1 = fmaf(a[4], r, fmaf(a[5], g, fmaf(a[6],  b, a[7])));
    float r2 = fmaf(a[8], r, fmaf(a[9], g, fmaf(a[10], b, a[11])));

    float* ro = out + (size_t)HW * 12 + (size_t)p * 3;
    ro[0] = r0;
    ro[1] = r1;
    ro[2] = r2;
}

extern "C" void kernel_launch(void* const* d_in, const int* in_sizes, int n_in,
                              void* d_out, int out_size)
{
    const float* rgb   = (const float*)d_in[0];
    const float* grids = (const float*)d_in[1];
    const int*   idx   = (const int*)d_in[2];
    float* out = (float*)d_out;

    dim3 grid(WI / BLK, HI);   // (15, 1080)
    bilateral_grid_kernel<<<grid, BLK>>>(rgb, grids, idx, out);
}